// round 1
// baseline (speedup 1.0000x reference)
#include <cuda_runtime.h>
#include <cuda_bf16.h>

// Problem shapes (fixed)
#define BB 16
#define CC 512
#define HWD 1024

// Scratch (device globals: the sanctioned no-alloc path)
__device__ float g_x[(size_t)BB * CC * HWD];   // 32 MB:  x[b,c,o]
__device__ float g_e[(size_t)BB * HWD * HWD];  // 64 MB:  e / a (softmax in-place)

// ---------------------------------------------------------------------------
// Classic SIMT fp32 GEMM: 128x128 tile, BK=8, 256 threads, 8x8 per-thread.
// OPA: 0 -> A[m*lda + k] (row-major MxK), 1 -> A[k*lda + m] (k-major)
// OPB: 0 -> B[k*ldb + n] (k-major KxN),   1 -> B[n*ldb + k] (row-major NxK)
// All dims assumed multiples of 128 / BK (true for this problem).
// ---------------------------------------------------------------------------
template <int OPA, int OPB>
__global__ __launch_bounds__(256) void sgemm_tile(
    const float* __restrict__ A, const float* __restrict__ B, float* __restrict__ C,
    int K, int lda, int ldb, int ldc,
    size_t sA, size_t sB, size_t sC)
{
    __shared__ float As[8][128];
    __shared__ float Bs[8][128];

    const int tid = threadIdx.x;
    A += (size_t)blockIdx.z * sA;
    B += (size_t)blockIdx.z * sB;
    C += (size_t)blockIdx.z * sC;

    const int bm = blockIdx.y * 128;
    const int bn = blockIdx.x * 128;

    const int tx = tid & 15;   // 16 columns of threads
    const int ty = tid >> 4;   // 16 rows of threads

    float acc[8][8];
    #pragma unroll
    for (int i = 0; i < 8; i++)
        #pragma unroll
        for (int j = 0; j < 8; j++)
            acc[i][j] = 0.0f;

    for (int kt = 0; kt < K; kt += 8) {
        // ---- load A tile into As[k][m] ----
        if (OPA == 0) {
            const int r = tid >> 1;            // m within tile: 0..127
            const int c = (tid & 1) * 4;       // k within tile: 0 or 4
            float4 v = *(const float4*)&A[(size_t)(bm + r) * lda + kt + c];
            As[c + 0][r] = v.x;
            As[c + 1][r] = v.y;
            As[c + 2][r] = v.z;
            As[c + 3][r] = v.w;
        } else {
            const int r = tid >> 5;            // k within tile: 0..7
            const int c = (tid & 31) * 4;      // m within tile: 0..124
            float4 v = *(const float4*)&A[(size_t)(kt + r) * lda + bm + c];
            *(float4*)&As[r][c] = v;
        }
        // ---- load B tile into Bs[k][n] ----
        if (OPB == 0) {
            const int r = tid >> 5;
            const int c = (tid & 31) * 4;
            float4 v = *(const float4*)&B[(size_t)(kt + r) * ldb + bn + c];
            *(float4*)&Bs[r][c] = v;
        } else {
            const int r = tid >> 1;            // n within tile
            const int c = (tid & 1) * 4;       // k within tile
            float4 v = *(const float4*)&B[(size_t)(bn + r) * ldb + kt + c];
            Bs[c + 0][r] = v.x;
            Bs[c + 1][r] = v.y;
            Bs[c + 2][r] = v.z;
            Bs[c + 3][r] = v.w;
        }
        __syncthreads();

        #pragma unroll
        for (int k = 0; k < 8; k++) {
            float ar[8], br[8];
            *(float4*)&ar[0] = *(const float4*)&As[k][ty * 8];
            *(float4*)&ar[4] = *(const float4*)&As[k][ty * 8 + 4];
            *(float4*)&br[0] = *(const float4*)&Bs[k][tx * 8];
            *(float4*)&br[4] = *(const float4*)&Bs[k][tx * 8 + 4];
            #pragma unroll
            for (int i = 0; i < 8; i++)
                #pragma unroll
                for (int j = 0; j < 8; j++)
                    acc[i][j] = fmaf(ar[i], br[j], acc[i][j]);
        }
        __syncthreads();
    }

    #pragma unroll
    for (int i = 0; i < 8; i++) {
        float* cp = &C[(size_t)(bm + ty * 8 + i) * ldc + bn + tx * 8];
        *(float4*)&cp[0] = make_float4(acc[i][0], acc[i][1], acc[i][2], acc[i][3]);
        *(float4*)&cp[4] = make_float4(acc[i][4], acc[i][5], acc[i][6], acc[i][7]);
    }
}

// ---------------------------------------------------------------------------
// In-place row softmax, row length 1024, one 256-thread block per row.
// ---------------------------------------------------------------------------
__global__ __launch_bounds__(256) void softmax1024(float* __restrict__ e)
{
    const size_t row = blockIdx.x;
    float* p = e + row * (size_t)HWD;
    const int t = threadIdx.x;

    float v[4];
    float mx = -1e30f;
    #pragma unroll
    for (int i = 0; i < 4; i++) {
        v[i] = p[t + 256 * i];
        mx = fmaxf(mx, v[i]);
    }

    __shared__ float redm[8];
    __shared__ float reds[8];

    #pragma unroll
    for (int o = 16; o > 0; o >>= 1)
        mx = fmaxf(mx, __shfl_xor_sync(0xFFFFFFFFu, mx, o));
    if ((t & 31) == 0) redm[t >> 5] = mx;
    __syncthreads();
    float m = redm[0];
    #pragma unroll
    for (int i = 1; i < 8; i++) m = fmaxf(m, redm[i]);

    float s = 0.0f;
    #pragma unroll
    for (int i = 0; i < 4; i++) {
        v[i] = __expf(v[i] - m);
        s += v[i];
    }
    #pragma unroll
    for (int o = 16; o > 0; o >>= 1)
        s += __shfl_xor_sync(0xFFFFFFFFu, s, o);
    if ((t & 31) == 0) reds[t >> 5] = s;
    __syncthreads();
    float sum = reds[0];
    #pragma unroll
    for (int i = 1; i < 8; i++) sum += reds[i];

    const float inv = 1.0f / sum;
    #pragma unroll
    for (int i = 0; i < 4; i++)
        p[t + 256 * i] = v[i] * inv;
}

// ---------------------------------------------------------------------------
// Launch: x = n1 @ Wc^T  ->  e = x^T @ n2 (per batch)  ->  softmax  ->
//         m = n2 @ a (per batch)
// ---------------------------------------------------------------------------
extern "C" void kernel_launch(void* const* d_in, const int* in_sizes, int n_in,
                              void* d_out, int out_size)
{
    const float* node1 = (const float*)d_in[0];  // [B, C, HW]
    const float* node2 = (const float*)d_in[1];  // [B, C, HW]
    const float* Wc    = (const float*)d_in[2];  // [HW, HW]
    float* out = (float*)d_out;                  // [B, C, HW]

    float *xptr = nullptr, *eptr = nullptr;
    cudaGetSymbolAddress((void**)&xptr, g_x);
    cudaGetSymbolAddress((void**)&eptr, g_e);

    dim3 blk(256);

    // GEMM1: x[m,o] = sum_h n1[m,h] * Wc[o,h]; M=B*C=8192, N=1024, K=1024 (NT)
    sgemm_tile<0, 1><<<dim3(HWD / 128, (BB * CC) / 128, 1), blk>>>(
        node1, Wc, xptr,
        HWD, HWD, HWD, HWD,
        0, 0, 0);

    // GEMM2: e[b,o,h] = sum_c x[b,c,o] * n2[b,c,h]; M=1024, N=1024, K=512 (TN)
    sgemm_tile<1, 0><<<dim3(HWD / 128, HWD / 128, BB), blk>>>(
        xptr, node2, eptr,
        CC, HWD, HWD, HWD,
        (size_t)CC * HWD, (size_t)CC * HWD, (size_t)HWD * HWD);

    // softmax over last dim, in place on g_e
    softmax1024<<<BB * HWD, 256>>>(eptr);

    // GEMM3: m[b,c,j] = sum_k n2[b,c,k] * a[b,k,j]; M=512, N=1024, K=1024 (NN)
    sgemm_tile<0, 0><<<dim3(HWD / 128, CC / 128, BB), blk>>>(
        node2, eptr, out,
        HWD, HWD, HWD, HWD,
        (size_t)CC * HWD, (size_t)HWD * HWD, (size_t)CC * HWD);
}

// round 3
// speedup vs baseline: 1.6078x; 1.6078x over previous
#include <cuda_runtime.h>
#include <cstdint>

#define BB 16
#define CC 512
#define HWD 1024

// Scratch (device globals)
__device__ float g_xT[(size_t)HWD * (BB * CC)];   // 32MB  xT[o][m], ld=8192
__device__ float g_e [(size_t)BB * HWD * HWD];    // 64MB  e[b][o][h] (softmax in place)
__device__ float g_n2T[(size_t)BB * HWD * CC];    // 32MB  n2T[b][h][c]
__device__ float g_aT [(size_t)BB * HWD * HWD];   // 64MB  aT[b][j][k]

// ---------------------------------------------------------------------------
#define GM_BM 128
#define GM_BN 128
#define GM_BK 16
#define GM_STAGES 3
#define GM_LDS 20                                  // smem row stride (floats)
#define GM_TILE_B (128 * GM_LDS * 4)               // 10240 B per tile
#define GM_STAGE_B (2 * GM_TILE_B)                 // A + B
#define GM_SMEM (GM_STAGES * GM_STAGE_B)           // 61440 B

__device__ __forceinline__ uint32_t smem_u32(const void* p) {
    uint32_t a;
    asm("{ .reg .u64 t; cvta.to.shared.u64 t, %1; cvt.u32.u64 %0, t; }" : "=r"(a) : "l"(p));
    return a;
}
__device__ __forceinline__ uint32_t cvt_tf32(float v) {
    uint32_t r;
    asm("cvt.rna.tf32.f32 %0, %1;" : "=r"(r) : "f"(v));
    return r;
}
__device__ __forceinline__ void cp16(uint32_t saddr, const float* g) {
    asm volatile("cp.async.ca.shared.global [%0], [%1], 16;" :: "r"(saddr), "l"(g));
}
__device__ __forceinline__ void cp_commit() {
    asm volatile("cp.async.commit_group;");
}
template <int N>
__device__ __forceinline__ void cp_wait() {
    asm volatile("cp.async.wait_group %0;" :: "n"(N));
}
__device__ __forceinline__ void mma8(float* d, const uint32_t* a, const uint32_t* b) {
    asm volatile(
        "mma.sync.aligned.m16n8k8.row.col.f32.tf32.tf32.f32 "
        "{%0,%1,%2,%3}, {%4,%5,%6,%7}, {%8,%9}, {%0,%1,%2,%3};"
        : "+f"(d[0]), "+f"(d[1]), "+f"(d[2]), "+f"(d[3])
        : "r"(a[0]), "r"(a[1]), "r"(a[2]), "r"(a[3]), "r"(b[0]), "r"(b[1]));
}

// ---------------------------------------------------------------------------
// C[m][n] = sum_k A[m][k] * B[n][k]  (both operands K-major).
// PASSES = 3: tf32x3 (fp32-class accuracy).  PASSES = 1: plain tf32.
// ---------------------------------------------------------------------------
template <int PASSES>
__global__ __launch_bounds__(256, 1) void gemm_tf32(
    const float* __restrict__ A, const float* __restrict__ B, float* __restrict__ C,
    int K, int lda, int ldb, int ldc, size_t sA, size_t sB, size_t sC)
{
    extern __shared__ float smem[];
    const uint32_t sbase = smem_u32(smem);

    const int tid = threadIdx.x;
    const int wid = tid >> 5;
    const int lane = tid & 31;
    const int warp_m = (wid & 1) * 64;   // 2 warps over M
    const int warp_n = (wid >> 1) * 32;  // 4 warps over N

    A += (size_t)blockIdx.z * sA;
    B += (size_t)blockIdx.z * sB;
    C += (size_t)blockIdx.z * sC;
    const int bm = blockIdx.y * GM_BM;
    const int bn = blockIdx.x * GM_BN;

    // global/shared coords for cp.async: 2 chunks of 16B each for A and B
    const int r0 = tid >> 2;            // rows 0..63 (p=0), 64..127 (p=1)
    const int q0 = (tid & 3) * 4;       // k offset within BK=16
    const float* Ag = A + (size_t)(bm + r0) * lda + q0;
    const float* Bg = B + (size_t)(bn + r0) * ldb + q0;

    const int nk = K / GM_BK;

    auto load_stage = [&](int kt, int s) {
        const uint32_t sa = sbase + s * GM_STAGE_B;
        const uint32_t sb = sa + GM_TILE_B;
        #pragma unroll
        for (int p = 0; p < 2; p++) {
            const int row = r0 + p * 64;
            cp16(sa + (row * GM_LDS + q0) * 4, Ag + (size_t)(p * 64) * lda + kt * GM_BK);
            cp16(sb + (row * GM_LDS + q0) * 4, Bg + (size_t)(p * 64) * ldb + kt * GM_BK);
        }
        cp_commit();
    };

    // prefetch STAGES-1 tiles
    load_stage(0, 0);
    load_stage(1, 1);

    float acc[4][4][4];
    #pragma unroll
    for (int i = 0; i < 4; i++)
        #pragma unroll
        for (int j = 0; j < 4; j++)
            #pragma unroll
            for (int t = 0; t < 4; t++)
                acc[i][j][t] = 0.0f;

    const int fr = lane >> 2;   // fragment row / n index
    const int fc = lane & 3;    // fragment k index

    for (int kt = 0; kt < nk; kt++) {
        cp_wait<GM_STAGES - 2>();
        __syncthreads();

        if (kt + 2 < nk) load_stage(kt + 2, (kt + 2) % GM_STAGES);

        const int s = kt % GM_STAGES;
        const float* As = smem + (size_t)s * GM_STAGE_B / 4;
        const float* Bs = As + GM_TILE_B / 4;

        #pragma unroll
        for (int k8 = 0; k8 < 2; k8++) {
            const int kb = k8 * 8;
            uint32_t Ah[4][4], Al[4][4], Bh[4][2], Bl[4][2];
            #pragma unroll
            for (int i = 0; i < 4; i++) {
                const int rr = warp_m + i * 16 + fr;
                #pragma unroll
                for (int t = 0; t < 4; t++) {
                    float v = As[(rr + (t & 1) * 8) * GM_LDS + kb + fc + (t >> 1) * 4];
                    Ah[i][t] = cvt_tf32(v);
                    if (PASSES == 3)
                        Al[i][t] = cvt_tf32(v - __uint_as_float(Ah[i][t]));
                }
            }
            #pragma unroll
            for (int j = 0; j < 4; j++) {
                const int nn = warp_n + j * 8 + fr;
                #pragma unroll
                for (int t = 0; t < 2; t++) {
                    float v = Bs[nn * GM_LDS + kb + fc + t * 4];
                    Bh[j][t] = cvt_tf32(v);
                    if (PASSES == 3)
                        Bl[j][t] = cvt_tf32(v - __uint_as_float(Bh[j][t]));
                }
            }
            // pass hi*hi
            #pragma unroll
            for (int i = 0; i < 4; i++)
                #pragma unroll
                for (int j = 0; j < 4; j++)
                    mma8(acc[i][j], Ah[i], Bh[j]);
            if (PASSES == 3) {
                #pragma unroll
                for (int i = 0; i < 4; i++)
                    #pragma unroll
                    for (int j = 0; j < 4; j++)
                        mma8(acc[i][j], Ah[i], Bl[j]);
                #pragma unroll
                for (int i = 0; i < 4; i++)
                    #pragma unroll
                    for (int j = 0; j < 4; j++)
                        mma8(acc[i][j], Al[i], Bh[j]);
            }
        }
        __syncthreads();
    }

    // epilogue
    #pragma unroll
    for (int i = 0; i < 4; i++) {
        const int row0 = bm + warp_m + i * 16 + fr;
        #pragma unroll
        for (int j = 0; j < 4; j++) {
            const int col = bn + warp_n + j * 8 + fc * 2;
            *(float2*)&C[(size_t)row0 * ldc + col] = make_float2(acc[i][j][0], acc[i][j][1]);
            *(float2*)&C[(size_t)(row0 + 8) * ldc + col] = make_float2(acc[i][j][2], acc[i][j][3]);
        }
    }
}

// ---------------------------------------------------------------------------
// Tiled transpose: in[z][R][Cc] -> out[z][Cc][R]
// ---------------------------------------------------------------------------
__global__ __launch_bounds__(256) void transpose_k(
    const float* __restrict__ in, float* __restrict__ out, int R, int Cc)
{
    __shared__ float t[32][33];
    const int bx = blockIdx.x * 32;
    const int by = blockIdx.y * 32;
    const float* ib = in + (size_t)blockIdx.z * R * Cc;
    float* ob = out + (size_t)blockIdx.z * R * Cc;
    const int x = threadIdx.x, y = threadIdx.y;  // 32 x 8
    #pragma unroll
    for (int i = 0; i < 32; i += 8)
        t[y + i][x] = ib[(size_t)(by + y + i) * Cc + bx + x];
    __syncthreads();
    #pragma unroll
    for (int i = 0; i < 32; i += 8)
        ob[(size_t)(bx + y + i) * R + by + x] = t[x][y + i];
}

// ---------------------------------------------------------------------------
// In-place row softmax, row length 1024
// ---------------------------------------------------------------------------
__global__ __launch_bounds__(256) void softmax1024(float* __restrict__ e)
{
    const size_t row = blockIdx.x;
    float* p = e + row * (size_t)HWD;
    const int t = threadIdx.x;

    float v[4];
    float mx = -1e30f;
    #pragma unroll
    for (int i = 0; i < 4; i++) {
        v[i] = p[t + 256 * i];
        mx = fmaxf(mx, v[i]);
    }
    __shared__ float redm[8];
    __shared__ float reds[8];
    #pragma unroll
    for (int o = 16; o > 0; o >>= 1)
        mx = fmaxf(mx, __shfl_xor_sync(0xFFFFFFFFu, mx, o));
    if ((t & 31) == 0) redm[t >> 5] = mx;
    __syncthreads();
    float m = redm[0];
    #pragma unroll
    for (int i = 1; i < 8; i++) m = fmaxf(m, redm[i]);

    float sacc = 0.0f;
    #pragma unroll
    for (int i = 0; i < 4; i++) {
        v[i] = __expf(v[i] - m);
        sacc += v[i];
    }
    #pragma unroll
    for (int o = 16; o > 0; o >>= 1)
        sacc += __shfl_xor_sync(0xFFFFFFFFu, sacc, o);
    if ((t & 31) == 0) reds[t >> 5] = sacc;
    __syncthreads();
    float sum = reds[0];
    #pragma unroll
    for (int i = 1; i < 8; i++) sum += reds[i];

    const float inv = 1.0f / sum;
    #pragma unroll
    for (int i = 0; i < 4; i++)
        p[t + 256 * i] = v[i] * inv;
}

// ---------------------------------------------------------------------------
extern "C" void kernel_launch(void* const* d_in, const int* in_sizes, int n_in,
                              void* d_out, int out_size)
{
    const float* node1 = (const float*)d_in[0];  // [B, C, HW]
    const float* node2 = (const float*)d_in[1];  // [B, C, HW]
    const float* Wc    = (const float*)d_in[2];  // [HW, HW]
    float* out = (float*)d_out;                  // [B, C, HW]

    float *xT, *e, *n2T, *aT;
    cudaGetSymbolAddress((void**)&xT,  g_xT);
    cudaGetSymbolAddress((void**)&e,   g_e);
    cudaGetSymbolAddress((void**)&n2T, g_n2T);
    cudaGetSymbolAddress((void**)&aT,  g_aT);

    cudaFuncSetAttribute(gemm_tf32<3>,
                         cudaFuncAttributeMaxDynamicSharedMemorySize, GM_SMEM);
    cudaFuncSetAttribute(gemm_tf32<1>,
                         cudaFuncAttributeMaxDynamicSharedMemorySize, GM_SMEM);

    // GEMM1: xT[o][m] = sum_h Wc[o][h] * n1[m][h];  M=1024, N=8192, K=1024
    gemm_tf32<3><<<dim3(8192 / GM_BN, HWD / GM_BM, 1), 256, GM_SMEM>>>(
        Wc, node1, xT, HWD, HWD, HWD, 8192, 0, 0, 0);

    // n2T[b][h][c] = n2[b][c][h]
    transpose_k<<<dim3(HWD / 32, CC / 32, BB), dim3(32, 8)>>>(node2, n2T, CC, HWD);

    // GEMM2: e[b][o][h] = sum_c xT[o][b*512+c] * n2T[b][h][c];  M=1024, N=1024, K=512
    gemm_tf32<3><<<dim3(HWD / GM_BN, HWD / GM_BM, BB), 256, GM_SMEM>>>(
        xT, n2T, e, CC, 8192, CC, HWD,
        (size_t)CC, (size_t)HWD * CC, (size_t)HWD * HWD);

    // softmax over h, in place
    softmax1024<<<BB * HWD, 256>>>(e);

    // aT[b][j][k] = a[b][k][j]
    transpose_k<<<dim3(HWD / 32, HWD / 32, BB), dim3(32, 8)>>>(e, aT, HWD, HWD);

    // GEMM3: out[b][c][j] = sum_k n2[b][c][k] * aT[b][j][k];  M=512, N=1024, K=1024
    gemm_tf32<1><<<dim3(HWD / GM_BN, CC / GM_BM, BB), 256, GM_SMEM>>>(
        node2, aT, out, HWD, HWD, HWD, HWD,
        (size_t)CC * HWD, (size_t)HWD * HWD, (size_t)CC * HWD);
}